// round 7
// baseline (speedup 1.0000x reference)
#include <cuda_runtime.h>
#include <math_constants.h>

// ============================================================================
// Chamfer loss: ONE persistent kernel, exact uniform-grid NN with CSR layout.
// Grid = #SMs (co-resident), software grid barriers, TPB=1024.
// P0 bbox+zero | P1 bin | P2 chunk scan | P3 offsets | P4 fill | P5 query.
// P5: 4 lanes/query fast path (exact when best <= cs^2). Escaping queries are
// processed WARP-COOPERATIVELY: 32 lanes load a 32-row band's CSR offsets in
// parallel, stream candidates 32-strided. Exact bounds: unscanned rows at
// |dy| have y-gap >= (dy-1)*cs; width W exact when (W*cs)^2 >= best, else
// widen & rescan (rare).
// ============================================================================

#define G      128
#define NCELL  (G * G)
#define TC     (2 * NCELL)
#define TMAX   65536
#define TPB    1024
#define NW     (TPB / 32)
#define MAXBLK 256
#define FULL   0xFFFFFFFFu

__device__ int          g_arr;
__device__ volatile int g_gen;
__device__ unsigned     g_blkbox[MAXBLK][4];
__device__ int          g_blksum[MAXBLK];
__device__ int          g_cnt[TC];
__device__ int          g_off[TC + 1];
__device__ int          g_cid[TMAX];
__device__ int          g_rank[TMAX];
__device__ float2       g_pts[TMAX];

static __device__ __forceinline__ unsigned f2ord(float f) {
    int b = __float_as_int(f);
    return (unsigned)b ^ (b < 0 ? 0xFFFFFFFFu : 0x80000000u);
}
static __device__ __forceinline__ float ord2f(unsigned u) {
    int b = (u & 0x80000000u) ? (int)(u ^ 0x80000000u) : (int)(~u);
    return __int_as_float(b);
}

static __device__ __forceinline__ void gridbar(int nblk) {
    __syncthreads();
    if (threadIdx.x == 0) {
        __threadfence();
        int g = g_gen;
        if (atomicAdd(&g_arr, 1) == nblk - 1) {
            g_arr = 0;
            __threadfence();
            g_gen = g + 1;
        } else {
            while (g_gen == g) { }   // hot spin: fastest wake
        }
    }
    __syncthreads();
}

// Block-wide exclusive scan; warp-uniform shfls, full masks.
static __device__ __forceinline__ int block_excl_scan(int v, int tid,
                                                      int* s_warp, int* total) {
    int lane = tid & 31, w = tid >> 5;
    int x = v;
#pragma unroll
    for (int o = 1; o < 32; o <<= 1) {
        int y = __shfl_up_sync(FULL, x, o);
        if (lane >= o) x += y;
    }
    if (lane == 31) s_warp[w] = x;
    __syncthreads();
    if (w == 0) {
        int y = (lane < NW) ? s_warp[lane] : 0;
#pragma unroll
        for (int o = 1; o < NW; o <<= 1) {
            int z = __shfl_up_sync(FULL, y, o);
            if (lane >= o) y += z;
        }
        if (lane < NW) s_warp[lane] = y;
    }
    __syncthreads();
    int base = w ? s_warp[w - 1] : 0;
    *total = s_warp[NW - 1];
    __syncthreads();
    return base + x - v;
}

static __device__ __forceinline__ int cell_of(float v, float o, float inv) {
    return min(G - 1, max(0, (int)((v - o) * inv)));
}

// Warp-cooperative exact NN for one escape query. All 32 lanes participate.
// Returns exact best (same value on all lanes).
static __device__ float warp_escape(float qx, float qy, float best, int cx, int cy,
                                    const int* __restrict__ off, int lane,
                                    float cs, float inv) {
    const float INF = CUDART_INF_F;
    int W = 12;
    for (;;) {
        if (best < INF) {
            int Wn = (int)(sqrtf(best) * inv) + 2;
            if (Wn > W) W = Wn;
        }
        if (W > G - 1) W = G - 1;
        int xlo = max(cx - W, 0), xhi = min(cx + W, G - 1);

        for (int dy0 = 0; ; dy0 += 16) {
            // lane 0..15  -> top rows    y = cy - (dy0 + lane)
            // lane 16..31 -> bottom rows y = cy + (dy0 + 1 + lane - 16)
            int y = (lane < 16) ? (cy - (dy0 + lane)) : (cy + (dy0 + 1 + (lane - 16)));
            int s0 = 0, e0 = 0;
            if (y >= 0 && y <= G - 1) {
                s0 = off[y * G + xlo];
                e0 = off[y * G + xhi + 1];
            }
            // Stream candidates: rows broadcast via shfl, 32-lane strided scan.
            for (int rr = 0; rr < 32; rr++) {
                int rs = __shfl_sync(FULL, s0, rr);
                int re = __shfl_sync(FULL, e0, rr);
                for (int k = rs + lane; k < re; k += 32) {
                    float2 p = g_pts[k];
                    float dx = qx - p.x, dyv = qy - p.y;
                    best = fminf(best, fmaf(dx, dx, dyv * dyv));
                }
            }
#pragma unroll
            for (int o = 16; o > 0; o >>= 1)
                best = fminf(best, __shfl_xor_sync(FULL, best, o));

            // Scanned: top dy in [0, dy0+15], bottom dy in [1, dy0+16].
            // Unscanned rows: top dy >= dy0+16 -> gap >= (dy0+15)*cs (the min).
            bool exhausted = (cy - (dy0 + 16) < 0) && (cy + (dy0 + 17) > G - 1);
            float bb = (float)(dy0 + 15) * cs;
            if (exhausted || (best < INF && bb * bb >= best)) break;
        }

        bool fullwidth = (xlo == 0 && xhi == G - 1);
        if (best < INF) {
            float wb = (float)W * cs;
            if (wb * wb >= best || fullwidth) break;
        } else if (fullwidth) {
            break;   // whole grid scanned (unreachable with nonempty target)
        }
        W <<= 1;     // width insufficient: widen & rescan (rare)
    }
    return best;
}

// ---------------------------------------------------------------------------
__global__ __launch_bounds__(TPB) void chamfer_fused(
    const float* __restrict__ A, int na,
    const float* __restrict__ B, int nb,
    float* __restrict__ out, int nblk)
{
    const int tid  = threadIdx.x;
    const int b    = blockIdx.x;
    const int gsz  = nblk * TPB;
    const int gtid = b * TPB + tid;
    const int total = na + nb;

    __shared__ int      s_warp[NW];
    __shared__ unsigned s_bb[4];
    __shared__ int      s_base;

    // ---------------- P0: zero counts, bbox partials, init out ----------------
    for (int i = gtid; i < TC; i += gsz) g_cnt[i] = 0;
    if (gtid == 0) { out[0] = 0.0f; g_off[TC] = total; }

    unsigned mnx = FULL, mny = FULL, mxx = 0u, mxy = 0u;
    for (int i = gtid; i < total; i += gsz) {
        const float2 p = (i < na) ? ((const float2*)A)[i]
                                  : ((const float2*)B)[i - na];
        unsigned ux = f2ord(p.x), uy = f2ord(p.y);
        mnx = min(mnx, ux); mny = min(mny, uy);
        mxx = max(mxx, ux); mxy = max(mxy, uy);
    }
#pragma unroll
    for (int o = 16; o > 0; o >>= 1) {
        mnx = min(mnx, __shfl_down_sync(FULL, mnx, o));
        mny = min(mny, __shfl_down_sync(FULL, mny, o));
        mxx = max(mxx, __shfl_down_sync(FULL, mxx, o));
        mxy = max(mxy, __shfl_down_sync(FULL, mxy, o));
    }
    {
        __shared__ unsigned sw[4][NW];
        int lane = tid & 31, w = tid >> 5;
        if (lane == 0) { sw[0][w] = mnx; sw[1][w] = mny; sw[2][w] = mxx; sw[3][w] = mxy; }
        __syncthreads();
        if (w == 0) {
            mnx = (lane < NW) ? sw[0][lane] : FULL;
            mny = (lane < NW) ? sw[1][lane] : FULL;
            mxx = (lane < NW) ? sw[2][lane] : 0u;
            mxy = (lane < NW) ? sw[3][lane] : 0u;
#pragma unroll
            for (int o = 16; o > 0; o >>= 1) {
                mnx = min(mnx, __shfl_down_sync(FULL, mnx, o));
                mny = min(mny, __shfl_down_sync(FULL, mny, o));
                mxx = max(mxx, __shfl_down_sync(FULL, mxx, o));
                mxy = max(mxy, __shfl_down_sync(FULL, mxy, o));
            }
            if (lane == 0) {
                g_blkbox[b][0] = mnx; g_blkbox[b][1] = mny;
                g_blkbox[b][2] = mxx; g_blkbox[b][3] = mxy;
            }
        }
    }
    gridbar(nblk);

    // ---------------- grid params ----------------
    if (tid < 32) {
        unsigned a0 = FULL, a1 = FULL, a2 = 0u, a3 = 0u;
        for (int k = tid; k < nblk; k += 32) {
            a0 = min(a0, g_blkbox[k][0]); a1 = min(a1, g_blkbox[k][1]);
            a2 = max(a2, g_blkbox[k][2]); a3 = max(a3, g_blkbox[k][3]);
        }
#pragma unroll
        for (int o = 16; o > 0; o >>= 1) {
            a0 = min(a0, __shfl_down_sync(FULL, a0, o));
            a1 = min(a1, __shfl_down_sync(FULL, a1, o));
            a2 = max(a2, __shfl_down_sync(FULL, a2, o));
            a3 = max(a3, __shfl_down_sync(FULL, a3, o));
        }
        if (tid == 0) { s_bb[0] = a0; s_bb[1] = a1; s_bb[2] = a2; s_bb[3] = a3; }
    }
    __syncthreads();
    const float x0 = ord2f(s_bb[0]);
    const float y0 = ord2f(s_bb[1]);
    const float L  = fmaxf(fmaxf(ord2f(s_bb[2]) - x0, ord2f(s_bb[3]) - y0), 1e-20f);
    const float cs = L / (float)G;
    const float inv = (float)G / L;

    // ---------------- P1: bin ----------------
    for (int i = gtid; i < total; i += gsz) {
        const float2 p = (i < na) ? ((const float2*)A)[i]
                                  : ((const float2*)B)[i - na];
        int s = (i < na) ? 0 : 1;
        int c = s * NCELL + cell_of(p.y, y0, inv) * G + cell_of(p.x, x0, inv);
        g_cid[i]  = c;
        g_rank[i] = atomicAdd(&g_cnt[c], 1);
    }
    gridbar(nblk);

    // ---------------- P2: per-block chunk scan ----------------
    const int cpb = (TC + nblk - 1) / nblk;   // 216 for nblk=152, <= TPB
    const int idx = b * cpb + tid;
    int v = (tid < cpb && idx < TC) ? g_cnt[idx] : 0;
    int btot;
    int excl = block_excl_scan(v, tid, s_warp, &btot);
    if (tid == 0) g_blksum[b] = btot;
    gridbar(nblk);

    // ---------------- P3: block bases -> CSR offsets ----------------
    {
        int bv = (tid < nblk) ? g_blksum[tid] : 0;
        int t2;
        int e2 = block_excl_scan(bv, tid, s_warp, &t2);
        if (tid == b) s_base = e2;
        __syncthreads();
        if (tid < cpb && idx < TC) g_off[idx] = s_base + excl;
    }
    gridbar(nblk);

    // ---------------- P4: scatter fill ----------------
    for (int i = gtid; i < total; i += gsz) {
        const float2 p = (i < na) ? ((const float2*)A)[i]
                                  : ((const float2*)B)[i - na];
        g_pts[g_off[g_cid[i]] + g_rank[i]] = p;
    }
    gridbar(nblk);

    // ---------------- P5: query (4 lanes/query; warp-coop escapes) ----------------
    float acc = 0.0f;
    const int ntask = 4 * total;
    const int lane  = tid & 31;
    const unsigned gmask = 0xFu << (lane & 28);
    const float INF = CUDART_INF_F;
    const float cs2 = cs * cs;

    // Warp-aligned task tiles: every lane of a warp iterates together.
    for (int tbase = (gtid >> 5) * 32; tbase < ntask; tbase += gsz) {
        int task = tbase + lane;
        bool valid = task < ntask;
        if (!valid) task = ntask - 1;   // clamped lanes form complete groups
        int q   = task >> 2;
        int sub = task & 3;
        float2 Q = g_pts[q];
        int cx = cell_of(Q.x, x0, inv);
        int cy = cell_of(Q.y, y0, inv);
        int offb = (q < na) ? NCELL : 0;
        const int* __restrict__ off = g_off + offb;

        float best = INF;

        // fast path: 3x3 = up to 3 contiguous row segments
        {
            int xlo = max(cx - 1, 0), xhi = min(cx + 1, G - 1);
            int ylo = max(cy - 1, 0), yhi = min(cy + 1, G - 1);
            for (int yy = ylo; yy <= yhi; yy++) {
                int s0 = off[yy * G + xlo], e0 = off[yy * G + xhi + 1];
                for (int k = s0 + sub; k < e0; k += 4) {
                    float2 p = g_pts[k];
                    float dx = Q.x - p.x, dy = Q.y - p.y;
                    best = fminf(best, fmaf(dx, dx, dy * dy));
                }
            }
        }
        best = fminf(best, __shfl_xor_sync(gmask, best, 1));
        best = fminf(best, __shfl_xor_sync(gmask, best, 2));

        // escapes: warp-cooperative, one query at a time
        bool esc = valid && !(best <= cs2);        // group-uniform
        unsigned eb = __ballot_sync(FULL, esc) & 0x11111111u;  // group leaders
        while (eb) {
            int src = __ffs(eb) - 1; eb &= eb - 1;
            float qx = __shfl_sync(FULL, Q.x, src);
            float qy = __shfl_sync(FULL, Q.y, src);
            float b0 = __shfl_sync(FULL, best, src);
            int ecx  = __shfl_sync(FULL, cx, src);
            int ecy  = __shfl_sync(FULL, cy, src);
            int eob  = __shfl_sync(FULL, offb, src);
            float nb = warp_escape(qx, qy, b0, ecx, ecy, g_off + eob,
                                   lane, cs, inv);
            if (lane == src) best = nb;
        }

        if (sub == 0 && valid) acc += sqrtf(best);
    }

    // Block sum -> one atomicAdd per block.
#pragma unroll
    for (int o = 16; o > 0; o >>= 1)
        acc += __shfl_down_sync(FULL, acc, o);
    {
        __shared__ float ws[NW];
        int w = tid >> 5;
        if (lane == 0) ws[w] = acc;
        __syncthreads();
        if (w == 0) {
            acc = (lane < NW) ? ws[lane] : 0.0f;
#pragma unroll
            for (int o = 16; o > 0; o >>= 1)
                acc += __shfl_down_sync(FULL, acc, o);
            if (lane == 0) atomicAdd(out, acc);
        }
    }
}

// ---------------------------------------------------------------------------
extern "C" void kernel_launch(void* const* d_in, const int* in_sizes, int n_in,
                              void* d_out, int out_size) {
    const float* A = (const float*)d_in[0];
    const float* B = (const float*)d_in[1];
    int na = in_sizes[0] / 2;
    int nb = in_sizes[1] / 2;
    float* out = (float*)d_out;

    int sms = 0;
    if (cudaDeviceGetAttribute(&sms, cudaDevAttrMultiProcessorCount, 0) != cudaSuccess
        || sms <= 0) sms = 148;
    int nblk = sms;
    if (nblk > MAXBLK) nblk = MAXBLK;
    if (nblk < 32)     nblk = 32;      // keep cpb <= TPB for the chunk scan

    chamfer_fused<<<nblk, TPB>>>(A, na, B, nb, out, nblk);
}